// round 1
// baseline (speedup 1.0000x reference)
#include <cuda_runtime.h>
#include <cstdint>

// Problem constants (fixed by setup_inputs: n=4096, d=2048, num_ids=256)
#define N        4096
#define D        2048
#define D4       512        // D / 4 floats per float4
#define NUM_IDS  256

// Scratch: gather indices for pair2 rows. [0..N): idx_pos, [N..2N): idx_neg.
__device__ int g_idx[2 * N];

// ---------------------------------------------------------------------------
// JAX Threefry-2x32 (20 rounds), matching jax._src.prng exactly.
// ---------------------------------------------------------------------------
__device__ __forceinline__ uint32_t rotl32(uint32_t v, int s) {
    return (v << s) | (v >> (32 - s));
}

__device__ __forceinline__ void threefry2x32(uint32_t k0, uint32_t k1,
                                             uint32_t x0, uint32_t x1,
                                             uint32_t& o0, uint32_t& o1) {
    const uint32_t ks2 = k0 ^ k1 ^ 0x1BD11BDAu;
    x0 += k0; x1 += k1;
#define TF_R4(a,b,c,d)                                        \
    x0 += x1; x1 = rotl32(x1,(a)); x1 ^= x0;                  \
    x0 += x1; x1 = rotl32(x1,(b)); x1 ^= x0;                  \
    x0 += x1; x1 = rotl32(x1,(c)); x1 ^= x0;                  \
    x0 += x1; x1 = rotl32(x1,(d)); x1 ^= x0;
    TF_R4(13,15,26,6)   x0 += k1;  x1 += ks2 + 1u;
    TF_R4(17,29,16,24)  x0 += ks2; x1 += k0  + 2u;
    TF_R4(13,15,26,6)   x0 += k0;  x1 += k1  + 3u;
    TF_R4(17,29,16,24)  x0 += k1;  x1 += ks2 + 4u;
    TF_R4(13,15,26,6)   x0 += ks2; x1 += k0  + 5u;
#undef TF_R4
    o0 = x0; o1 = x1;
}

// jax _uniform: bitcast((bits>>9) | 0x3f800000) - 1.0  ->  [0, 1)
__device__ __forceinline__ float bits_to_uniform(uint32_t bits) {
    return __uint_as_float((bits >> 9) | 0x3f800000u) - 1.0f;
}

// Partitionable threefry random_bits for 32-bit, index i (< 2^32):
// counts = 64-bit iota -> (hi=0, lo=i); bits = o0 ^ o1.
__device__ __forceinline__ uint32_t jax_random_bits32(uint32_t seed_lo, uint32_t i) {
    uint32_t o0, o1;
    threefry2x32(0u, seed_lo, 0u, i, o0, o1);
    return o0 ^ o1;
}

// ---------------------------------------------------------------------------
// Kernel 1: histogram of targets -> per-row counts -> sampled indices.
// Single block; negligible cost vs. the streaming pass.
// ---------------------------------------------------------------------------
__global__ void setup_indices_kernel(const int* __restrict__ targets) {
    __shared__ int hist[NUM_IDS];
    const int t = threadIdx.x;

    for (int i = t; i < NUM_IDS; i += blockDim.x) hist[i] = 0;
    __syncthreads();
    for (int i = t; i < N; i += blockDim.x) atomicAdd(&hist[targets[i]], 1);
    __syncthreads();

    for (int i = t; i < N; i += blockDim.x) {
        const float up = bits_to_uniform(jax_random_bits32(1u, (uint32_t)i));
        const float un = bits_to_uniform(jax_random_bits32(2u, (uint32_t)i));

        const int pc = hist[targets[i]];            // >= 1 (self)
        int nc = N - pc; if (nc < 1) nc = 1;        // jnp.maximum(n - pos, 1)

        // idx = min(trunc_f32(u * count), count - 1): single RN fmul + RZ cvt,
        // identical to jnp's (u * counts).astype(int32).
        int ip = (int)(__fmul_rn(up, (float)pc));
        if (ip > pc - 1) ip = pc - 1;
        int in_ = (int)(__fmul_rn(un, (float)nc));
        if (in_ > nc - 1) in_ = nc - 1;

        g_idx[i]     = ip;   // pair2 row i      = inputs[idx_pos[i]]
        g_idx[N + i] = in_;  // pair2 row N + i  = inputs[idx_neg[i]]
    }
}

// ---------------------------------------------------------------------------
// Kernel 2: one float4 per thread.
//   region A [0, T1):        v = in[k];  out[k] = v; out[T1+k] = v   (pair1)
//   region B [T1, T1+T2):    out[T2 + j] = in[g_idx[row(j)]]         (pair2)
//   region C tail (2N thr):  y = [1^N ; 0^N]
// ---------------------------------------------------------------------------
__global__ void __launch_bounds__(256)
fill_output_kernel(const float4* __restrict__ in4, float4* __restrict__ out4) {
    const int  T1  = N * D4;        // 2,097,152 float4  (one copy of inputs)
    const int  T2  = 2 * N * D4;    // 4,194,304 float4  (pair2 size)
    const long tid = (long)blockIdx.x * blockDim.x + threadIdx.x;

    if (tid < T1) {
        const float4 v = in4[tid];
        out4[tid]      = v;          // pair1 top half:    inputs
        out4[T1 + tid] = v;          // pair1 bottom half: inputs (read once)
    } else if (tid < (long)T1 + T2) {
        const int j = (int)(tid - T1);
        const int r = j >> 9;            // pair2 row (0..2N)
        const int c = j & (D4 - 1);      // float4 column
        out4[T2 + j] = __ldg(&in4[(long)g_idx[r] * D4 + c]);
    } else {
        const int i = (int)(tid - (long)T1 - T2);
        if (i < 2 * N) {
            float* y = (float*)(out4 + (long)2 * T2);   // after pair1+pair2
            y[i] = (i < N) ? 1.0f : 0.0f;
        }
    }
}

// ---------------------------------------------------------------------------
extern "C" void kernel_launch(void* const* d_in, const int* in_sizes, int n_in,
                              void* d_out, int out_size) {
    const float* inputs  = (const float*)d_in[0];   // [N, D] f32
    const int*   targets = (const int*)d_in[1];     // [N] i32
    (void)in_sizes; (void)n_in; (void)out_size;

    setup_indices_kernel<<<1, 512>>>(targets);

    const long total_threads = (long)N * D4        // region A
                             + (long)2 * N * D4    // region B
                             + 2 * N;              // region C (y)
    const int threads = 256;
    const int blocks  = (int)((total_threads + threads - 1) / threads);
    fill_output_kernel<<<blocks, threads>>>((const float4*)inputs, (float4*)d_out);
}

// round 4
// speedup vs baseline: 1.2796x; 1.2796x over previous
#include <cuda_runtime.h>
#include <cstdint>

// Problem constants (fixed by setup_inputs: n=4096, d=2048, num_ids=256)
#define N        4096
#define D        2048
#define D4       512        // float4 per row
#define NUM_IDS  256

// Scratch (device globals — no allocation allowed)
__device__ int g_hist[NUM_IDS];
__device__ int g_idx[2 * N];   // [0..N): idx_pos, [N..2N): idx_neg

// ---------------------------------------------------------------------------
// JAX Threefry-2x32 (20 rounds), matching jax._src.prng exactly.
// ---------------------------------------------------------------------------
__device__ __forceinline__ uint32_t rotl32(uint32_t v, int s) {
    return (v << s) | (v >> (32 - s));
}

__device__ __forceinline__ void threefry2x32(uint32_t k0, uint32_t k1,
                                             uint32_t x0, uint32_t x1,
                                             uint32_t& o0, uint32_t& o1) {
    const uint32_t ks2 = k0 ^ k1 ^ 0x1BD11BDAu;
    x0 += k0; x1 += k1;
#define TF_R4(a,b,c,d)                                        \
    x0 += x1; x1 = rotl32(x1,(a)); x1 ^= x0;                  \
    x0 += x1; x1 = rotl32(x1,(b)); x1 ^= x0;                  \
    x0 += x1; x1 = rotl32(x1,(c)); x1 ^= x0;                  \
    x0 += x1; x1 = rotl32(x1,(d)); x1 ^= x0;
    TF_R4(13,15,26,6)   x0 += k1;  x1 += ks2 + 1u;
    TF_R4(17,29,16,24)  x0 += ks2; x1 += k0  + 2u;
    TF_R4(13,15,26,6)   x0 += k0;  x1 += k1  + 3u;
    TF_R4(17,29,16,24)  x0 += k1;  x1 += ks2 + 4u;
    TF_R4(13,15,26,6)   x0 += ks2; x1 += k0  + 5u;
#undef TF_R4
    o0 = x0; o1 = x1;
}

__device__ __forceinline__ float bits_to_uniform(uint32_t bits) {
    return __uint_as_float((bits >> 9) | 0x3f800000u) - 1.0f;
}

__device__ __forceinline__ uint32_t jax_random_bits32(uint32_t seed_lo, uint32_t i) {
    uint32_t o0, o1;
    threefry2x32(0u, seed_lo, 0u, i, o0, o1);
    return o0 ^ o1;
}

// ---------------------------------------------------------------------------
// Kernel 1: histogram of targets (single block, shared memory -> global).
// ---------------------------------------------------------------------------
__global__ void __launch_bounds__(1024)
hist_kernel(const int* __restrict__ targets) {
    __shared__ int hist[NUM_IDS];
    const int t = threadIdx.x;
    if (t < NUM_IDS) hist[t] = 0;
    __syncthreads();
    for (int i = t; i < N; i += 1024) atomicAdd(&hist[targets[i]], 1);
    __syncthreads();
    if (t < NUM_IDS) g_hist[t] = hist[t];
}

// ---------------------------------------------------------------------------
// Kernel 2: one thread per row -> threefry indices. Also writes y.
// 32 blocks x 128 threads = 4096 threads.
// ---------------------------------------------------------------------------
__global__ void __launch_bounds__(128)
index_kernel(const int* __restrict__ targets, float* __restrict__ y) {
    const int i = blockIdx.x * 128 + threadIdx.x;   // 0..N-1

    const float up = bits_to_uniform(jax_random_bits32(1u, (uint32_t)i));
    const float un = bits_to_uniform(jax_random_bits32(2u, (uint32_t)i));

    const int pc = g_hist[targets[i]];          // >= 1 (self)
    int nc = N - pc; if (nc < 1) nc = 1;        // jnp.maximum(n - pos, 1)

    int ip = (int)(__fmul_rn(up, (float)pc));
    if (ip > pc - 1) ip = pc - 1;
    int in_ = (int)(__fmul_rn(un, (float)nc));
    if (in_ > nc - 1) in_ = nc - 1;

    g_idx[i]     = ip;
    g_idx[N + i] = in_;

    // y = [1^N ; 0^N]
    y[i]     = 1.0f;
    y[N + i] = 0.0f;
}

// ---------------------------------------------------------------------------
// Kernel 3: streaming fill. Block-uniform regions, 4 float4 loads per thread.
//   blocks [0, 2048):     pair1 — 2 input rows per block, read once store twice
//   blocks [2048, 6144):  pair2 — 2 gather rows per block via g_idx
// All output stores use __stcs (evict-first) so the 33.5MB input stays
// L2-resident against 134MB of streaming writes.
// ---------------------------------------------------------------------------
__global__ void __launch_bounds__(256)
fill_output_kernel(const float4* __restrict__ in4, float4* __restrict__ out4) {
    const int T1 = N * D4;        // 2,097,152 float4  (one copy of inputs)
    const int T2 = 2 * N * D4;    // 4,194,304 float4  (pair1 total = pair2 total)
    const int b  = blockIdx.x;
    const int t  = threadIdx.x;

    if (b < 2048) {
        // pair1: block covers 1024 consecutive float4 (2 input rows)
        const int base = b * 1024;
        const float4 v0 = __ldg(&in4[base + t]);
        const float4 v1 = __ldg(&in4[base + t + 256]);
        const float4 v2 = __ldg(&in4[base + t + 512]);
        const float4 v3 = __ldg(&in4[base + t + 768]);
        __stcs(&out4[base + t],            v0);   // top half: inputs
        __stcs(&out4[base + t + 256],      v1);
        __stcs(&out4[base + t + 512],      v2);
        __stcs(&out4[base + t + 768],      v3);
        __stcs(&out4[T1 + base + t],       v0);   // bottom half: inputs again
        __stcs(&out4[T1 + base + t + 256], v1);
        __stcs(&out4[T1 + base + t + 512], v2);
        __stcs(&out4[T1 + base + t + 768], v3);
    } else {
        // pair2: 2 gather rows per block (uniform g_idx loads per block)
        const int r0   = (b - 2048) * 2;          // 0..2N-1
        const int r1   = r0 + 1;
        const int s0   = g_idx[r0] * D4;
        const int s1   = g_idx[r1] * D4;
        const float4 v0 = __ldg(&in4[s0 + t]);
        const float4 v1 = __ldg(&in4[s0 + t + 256]);
        const float4 v2 = __ldg(&in4[s1 + t]);
        const float4 v3 = __ldg(&in4[s1 + t + 256]);
        __stcs(&out4[T2 + r0 * D4 + t],       v0);
        __stcs(&out4[T2 + r0 * D4 + t + 256], v1);
        __stcs(&out4[T2 + r1 * D4 + t],       v2);
        __stcs(&out4[T2 + r1 * D4 + t + 256], v3);
    }
}

// ---------------------------------------------------------------------------
extern "C" void kernel_launch(void* const* d_in, const int* in_sizes, int n_in,
                              void* d_out, int out_size) {
    const float* inputs  = (const float*)d_in[0];   // [N, D] f32
    const int*   targets = (const int*)d_in[1];     // [N] i32
    (void)in_sizes; (void)n_in; (void)out_size;

    // y lives after pair1 (2N*D floats) + pair2 (2N*D floats)
    float* y = (float*)d_out + (size_t)4 * N * D;

    hist_kernel<<<1, 1024>>>(targets);
    index_kernel<<<32, 128>>>(targets, y);
    fill_output_kernel<<<6144, 256>>>((const float4*)inputs, (float4*)d_out);
}